// round 1
// baseline (speedup 1.0000x reference)
#include <cuda_runtime.h>
#include <cuda_bf16.h>
#include <cstdint>

// ============================================================================
// 2-layer LSTM (H=32, T=7, F=1) + Linear(H,1) + Linear(T,1), B=262144.
// One thread per batch element. Packed f32x2 FMA (Blackwell) for gate GEMVs.
// Weights transposed+pair-packed in SMEM (broadcast LDS). h-state in regs,
// c-state + h-staging in per-thread SMEM slots so the gate-chunk loop stays
// rolled (small I-footprint).
// ============================================================================

typedef unsigned long long u64;

__device__ __forceinline__ u64 pk2(float lo, float hi) {
    u64 r; asm("mov.b64 %0,{%1,%2};" : "=l"(r) : "f"(lo), "f"(hi)); return r;
}
__device__ __forceinline__ u64 bc2(float v) { return pk2(v, v); }
__device__ __forceinline__ void upk2(u64 v, float& lo, float& hi) {
    asm("mov.b64 {%0,%1},%2;" : "=f"(lo), "=f"(hi) : "l"(v));
}
__device__ __forceinline__ u64 fma2(u64 a, u64 b, u64 c) {
    u64 d; asm("fma.rn.f32x2 %0,%1,%2,%3;" : "=l"(d) : "l"(a), "l"(b), "l"(c)); return d;
}
__device__ __forceinline__ u64 mul2(u64 a, u64 b) {
    u64 d; asm("mul.rn.f32x2 %0,%1,%2;" : "=l"(d) : "l"(a), "l"(b)); return d;
}
__device__ __forceinline__ float ex2f(float x) {
    float y; asm("ex2.approx.f32 %0,%1;" : "=f"(y) : "f"(x)); return y;
}
__device__ __forceinline__ float rcpf(float x) {
    float y; asm("rcp.approx.f32 %0,%1;" : "=f"(y) : "f"(x)); return y;
}
// sigmoid(x) = 1/(1+2^(-x*log2e)).  x->+inf: e=0 -> 1.  x->-inf: e=inf -> rcp(inf)=0. OK.
__device__ __forceinline__ float fsig(float x) {
    float e = ex2f(-1.4426950408889634f * x);
    return rcpf(1.0f + e);
}
// tanh(x) = (1-e)/(1+e), e = 2^(-2x*log2e). Clamp exponent to avoid inf*0 NaN.
__device__ __forceinline__ float ftanhx(float x) {
    float t = fminf(-2.8853900817779268f * x, 120.0f);
    float e = ex2f(t);
    float r = rcpf(1.0f + e);
    return fmaf(-e, r, r);
}
__device__ __forceinline__ u64 sig2(u64 z) {
    float a, b; upk2(z, a, b); return pk2(fsig(a), fsig(b));
}
__device__ __forceinline__ u64 tanh2(u64 z) {
    float a, b; upk2(z, a, b); return pk2(ftanhx(a), ftanhx(b));
}

// Gate update for one unit-pair. z* are packed (unit 2u, 2u+1) preactivations.
template <bool DOACC>
__device__ __forceinline__ void lstm_update(
    u64 zi, u64 zf, u64 zg, u64 zo,
    u64* cslot, float* hn_lo, float* hn_hi,
    u64 wo, u64& acc)
{
    u64 i2 = sig2(zi);
    u64 f2 = sig2(zf);
    u64 g2 = tanh2(zg);
    u64 o2 = sig2(zo);
    u64 cc = *cslot;
    cc = fma2(f2, cc, mul2(i2, g2));
    *cslot = cc;
    u64 h2 = mul2(o2, tanh2(cc));
    if (DOACC) acc = fma2(h2, wo, acc);
    float lo, hi; upk2(h2, lo, hi);
    *hn_lo = lo; *hn_hi = hi;
}

// Dynamic SMEM layout (in u64 units):
//   U0  [32][64]  : W_hh0 transposed, float view U0f[k*128 + j] = Whh0[j][k]   (2048)
//   WX1 [32][64]  : W_ih1 transposed                                           (2048)
//   WH1 [32][64]  : W_hh1 transposed                                           (2048)
//   B0  [64]      : (b_ih0 + b_hh0) pair-packed                                (64)
//   WI0 [64]      : W_ih0[:,0] pair-packed                                     (64)
//   B1  [64]      : (b_ih1 + b_hh1) pair-packed                                (64)
//   WO  [7][16]   : fc1_w[t]*fc_w[h] pair-packed                               (112)
//   C0  [16][128] : layer-0 cell state, per-thread packed pairs                (2048)
//   C1  [16][128] : layer-1 cell state                                         (2048)
//   HN  (float[32][128]) : per-thread h staging                                (2048)
// total = 12592 u64 = 100736 bytes
#define SMEM_U64S 12592
#define SMEM_BYTES (SMEM_U64S * 8)

extern "C" __global__ void __launch_bounds__(128, 2)
lstm_b262144_kernel(
    const float* __restrict__ x,
    const float* __restrict__ Wih0, const float* __restrict__ Whh0,
    const float* __restrict__ bih0, const float* __restrict__ bhh0,
    const float* __restrict__ Wih1, const float* __restrict__ Whh1,
    const float* __restrict__ bih1, const float* __restrict__ bhh1,
    const float* __restrict__ fcw,  const float* __restrict__ fcb,
    const float* __restrict__ fc1w, const float* __restrict__ fc1b,
    float* __restrict__ out, int B)
{
    extern __shared__ u64 sm[];
    u64* U0  = sm;
    u64* WX1 = U0 + 2048;
    u64* WH1 = WX1 + 2048;
    u64* B0  = WH1 + 2048;
    u64* WI0 = B0 + 64;
    u64* B1  = WI0 + 64;
    u64* WO  = B1 + 64;
    u64* C0  = WO + 112;
    u64* C1  = C0 + 2048;
    float* HN = (float*)(C1 + 2048);

    const int tid = threadIdx.x;

    // ---- cooperative SMEM fill (weights transposed: dst[k*128 + j] = W[j*32 + k]) ----
    {
        float* U0f  = (float*)U0;
        float* WX1f = (float*)WX1;
        float* WH1f = (float*)WH1;
        for (int d = tid; d < 4096; d += 128) {
            int k = d >> 7, j = d & 127;
            U0f[d]  = Whh0[j * 32 + k];
            WX1f[d] = Wih1[j * 32 + k];
            WH1f[d] = Whh1[j * 32 + k];
        }
        float* B0f  = (float*)B0;
        float* WI0f = (float*)WI0;
        float* B1f  = (float*)B1;
        if (tid < 128) {
            B0f[tid]  = bih0[tid] + bhh0[tid];
            WI0f[tid] = Wih0[tid];          // [128,1]
            B1f[tid]  = bih1[tid] + bhh1[tid];
        }
        float* WOf = (float*)WO;
        for (int d = tid; d < 224; d += 128) {
            int t = d >> 5, h = d & 31;
            WOf[d] = fc1w[t] * fcw[h];
        }
    }
    __syncthreads();

    const int b = blockIdx.x * 128 + tid;
    if (b >= B) return;

    // zero per-thread cell state
#pragma unroll
    for (int u = 0; u < 16; u++) { C0[u * 128 + tid] = 0ull; C1[u * 128 + tid] = 0ull; }

    float h0[32], h1[32];
#pragma unroll
    for (int k = 0; k < 32; k++) { h0[k] = 0.0f; h1[k] = 0.0f; }

    u64 acc = 0ull;  // packed (0,0): Σ_t Σ_h wo[t][h] * h2[t][h]
    u64 dummy = 0ull;

#pragma unroll 1
    for (int t = 0; t < 7; t++) {
        u64 x2 = bc2(x[(long long)b * 7 + t]);

        // ================= layer 0 (in = scalar x_t, hidden = h0) =================
#pragma unroll 1
        for (int c = 0; c < 8; c++) {
            const int p0 = 2 * c;
            u64 zi0 = fma2(x2, WI0[p0 + 0],  B0[p0 + 0]);
            u64 zi1 = fma2(x2, WI0[p0 + 1],  B0[p0 + 1]);
            u64 zf0 = fma2(x2, WI0[p0 + 16], B0[p0 + 16]);
            u64 zf1 = fma2(x2, WI0[p0 + 17], B0[p0 + 17]);
            u64 zg0 = fma2(x2, WI0[p0 + 32], B0[p0 + 32]);
            u64 zg1 = fma2(x2, WI0[p0 + 33], B0[p0 + 33]);
            u64 zo0 = fma2(x2, WI0[p0 + 48], B0[p0 + 48]);
            u64 zo1 = fma2(x2, WI0[p0 + 49], B0[p0 + 49]);
            const u64* w = U0 + p0;
#pragma unroll
            for (int k = 0; k < 32; k++) {
                u64 hk = bc2(h0[k]);
                zi0 = fma2(hk, w[0],  zi0); zi1 = fma2(hk, w[1],  zi1);
                zf0 = fma2(hk, w[16], zf0); zf1 = fma2(hk, w[17], zf1);
                zg0 = fma2(hk, w[32], zg0); zg1 = fma2(hk, w[33], zg1);
                zo0 = fma2(hk, w[48], zo0); zo1 = fma2(hk, w[49], zo1);
                w += 64;
            }
            lstm_update<false>(zi0, zf0, zg0, zo0, C0 + p0 * 128 + tid,
                               &HN[(2 * p0 + 0) * 128 + tid], &HN[(2 * p0 + 1) * 128 + tid],
                               0ull, dummy);
            lstm_update<false>(zi1, zf1, zg1, zo1, C0 + (p0 + 1) * 128 + tid,
                               &HN[(2 * p0 + 2) * 128 + tid], &HN[(2 * p0 + 3) * 128 + tid],
                               0ull, dummy);
        }
#pragma unroll
        for (int k = 0; k < 32; k++) h0[k] = HN[k * 128 + tid];

        // ================= layer 1 (in = h0(new), hidden = h1) =================
#pragma unroll 1
        for (int c = 0; c < 8; c++) {
            const int p0 = 2 * c;
            u64 zi0 = B1[p0 + 0],  zi1 = B1[p0 + 1];
            u64 zf0 = B1[p0 + 16], zf1 = B1[p0 + 17];
            u64 zg0 = B1[p0 + 32], zg1 = B1[p0 + 33];
            u64 zo0 = B1[p0 + 48], zo1 = B1[p0 + 49];
            const u64* w = WX1 + p0;
#pragma unroll
            for (int k = 0; k < 32; k++) {
                u64 hk = bc2(h0[k]);
                zi0 = fma2(hk, w[0],  zi0); zi1 = fma2(hk, w[1],  zi1);
                zf0 = fma2(hk, w[16], zf0); zf1 = fma2(hk, w[17], zf1);
                zg0 = fma2(hk, w[32], zg0); zg1 = fma2(hk, w[33], zg1);
                zo0 = fma2(hk, w[48], zo0); zo1 = fma2(hk, w[49], zo1);
                w += 64;
            }
            w = WH1 + p0;
#pragma unroll
            for (int k = 0; k < 32; k++) {
                u64 hk = bc2(h1[k]);
                zi0 = fma2(hk, w[0],  zi0); zi1 = fma2(hk, w[1],  zi1);
                zf0 = fma2(hk, w[16], zf0); zf1 = fma2(hk, w[17], zf1);
                zg0 = fma2(hk, w[32], zg0); zg1 = fma2(hk, w[33], zg1);
                zo0 = fma2(hk, w[48], zo0); zo1 = fma2(hk, w[49], zo1);
                w += 64;
            }
            lstm_update<true>(zi0, zf0, zg0, zo0, C1 + p0 * 128 + tid,
                              &HN[(2 * p0 + 0) * 128 + tid], &HN[(2 * p0 + 1) * 128 + tid],
                              WO[t * 16 + p0], acc);
            lstm_update<true>(zi1, zf1, zg1, zo1, C1 + (p0 + 1) * 128 + tid,
                              &HN[(2 * p0 + 2) * 128 + tid], &HN[(2 * p0 + 3) * 128 + tid],
                              WO[t * 16 + p0 + 1], acc);
        }
#pragma unroll
        for (int k = 0; k < 32; k++) h1[k] = HN[k * 128 + tid];
    }

    // y = acc.lo + acc.hi + fc_b*Σ_t fc1_w[t] + fc1_b
    float alo, ahi; upk2(acc, alo, ahi);
    float s = 0.0f;
#pragma unroll
    for (int t = 0; t < 7; t++) s += fc1w[t];
    out[b] = alo + ahi + fcb[0] * s + fc1b[0];
}

extern "C" void kernel_launch(void* const* d_in, const int* in_sizes, int n_in,
                              void* d_out, int out_size) {
    const float* x    = (const float*)d_in[0];
    const float* Wih0 = (const float*)d_in[1];
    const float* Whh0 = (const float*)d_in[2];
    const float* bih0 = (const float*)d_in[3];
    const float* bhh0 = (const float*)d_in[4];
    const float* Wih1 = (const float*)d_in[5];
    const float* Whh1 = (const float*)d_in[6];
    const float* bih1 = (const float*)d_in[7];
    const float* bhh1 = (const float*)d_in[8];
    const float* fcw  = (const float*)d_in[9];
    const float* fcb  = (const float*)d_in[10];
    const float* fc1w = (const float*)d_in[11];
    const float* fc1b = (const float*)d_in[12];
    float* out = (float*)d_out;

    const int B = in_sizes[0] / 7;  // [B, T=7, F=1]

    // idempotent; required for >48KB dynamic smem
    cudaFuncSetAttribute(lstm_b262144_kernel,
                         cudaFuncAttributeMaxDynamicSharedMemorySize, SMEM_BYTES);

    int grid = (B + 127) / 128;
    lstm_b262144_kernel<<<grid, 128, SMEM_BYTES>>>(
        x, Wih0, Whh0, bih0, bhh0, Wih1, Whh1, bih1, bhh1,
        fcw, fcb, fc1w, fc1b, out, B);
}

// round 2
// speedup vs baseline: 1.0620x; 1.0620x over previous
#include <cuda_runtime.h>
#include <cuda_bf16.h>
#include <cstdint>

// ============================================================================
// 2-layer LSTM (H=32, T=7, F=1) + Linear(H,1) + Linear(T,1), B=262144.
// R2: TWO batch elements per thread + LDS.128 weight fetches.
// Weights repacked in SMEM: for (chunk c, k) the 8 gate-pair u64 weights are
// contiguous (64B) -> 4x LDS.128 broadcast feeds 16 FFMA2 (2 elems x 8 gates).
// h-state in registers (fully unrolled k loops); c-state + h staging in
// per-thread SMEM slots so chunk loops stay rolled (small I-footprint).
// ============================================================================

typedef unsigned long long u64;

__device__ __forceinline__ u64 pk2(float lo, float hi) {
    u64 r; asm("mov.b64 %0,{%1,%2};" : "=l"(r) : "f"(lo), "f"(hi)); return r;
}
__device__ __forceinline__ u64 bc2(float v) { return pk2(v, v); }
__device__ __forceinline__ void upk2(u64 v, float& lo, float& hi) {
    asm("mov.b64 {%0,%1},%2;" : "=f"(lo), "=f"(hi) : "l"(v));
}
__device__ __forceinline__ u64 fma2(u64 a, u64 b, u64 c) {
    u64 d; asm("fma.rn.f32x2 %0,%1,%2,%3;" : "=l"(d) : "l"(a), "l"(b), "l"(c)); return d;
}
__device__ __forceinline__ u64 mul2(u64 a, u64 b) {
    u64 d; asm("mul.rn.f32x2 %0,%1,%2;" : "=l"(d) : "l"(a), "l"(b)); return d;
}
__device__ __forceinline__ float ex2f(float x) {
    float y; asm("ex2.approx.f32 %0,%1;" : "=f"(y) : "f"(x)); return y;
}
__device__ __forceinline__ float rcpf(float x) {
    float y; asm("rcp.approx.f32 %0,%1;" : "=f"(y) : "f"(x)); return y;
}
__device__ __forceinline__ float fsig(float x) {
    float e = ex2f(-1.4426950408889634f * x);
    return rcpf(1.0f + e);
}
__device__ __forceinline__ float ftanhx(float x) {
    float t = fminf(-2.8853900817779268f * x, 120.0f);
    float e = ex2f(t);
    float r = rcpf(1.0f + e);
    return fmaf(-e, r, r);
}
__device__ __forceinline__ u64 sig2(u64 z) {
    float a, b; upk2(z, a, b); return pk2(fsig(a), fsig(b));
}
__device__ __forceinline__ u64 tanh2(u64 z) {
    float a, b; upk2(z, a, b); return pk2(ftanhx(a), ftanhx(b));
}

// One unit-pair gate update. z* packed (unit 2p, 2p+1) preactivations.
template <bool DOACC>
__device__ __forceinline__ void lstm_update(
    u64 zi, u64 zf, u64 zg, u64 zo,
    u64* cslot, float* hn_lo, float* hn_hi,
    u64 wo, u64& acc)
{
    u64 i2 = sig2(zi);
    u64 f2 = sig2(zf);
    u64 g2 = tanh2(zg);
    u64 o2 = sig2(zo);
    u64 cc = *cslot;
    cc = fma2(f2, cc, mul2(i2, g2));
    *cslot = cc;
    u64 h2 = mul2(o2, tanh2(cc));
    if (DOACC) acc = fma2(h2, wo, acc);
    float lo, hi; upk2(h2, lo, hi);
    *hn_lo = lo; *hn_hi = hi;
}

// SMEM layout (u64 units):
//  WL0  [8c][32k][8s] repacked Whh0   2048
//  WLX1 [8c][32k][8s] repacked Wih1   2048
//  WLH1 [8c][32k][8s] repacked Whh1   2048
//  B0   [64]  (b_ih0+b_hh0) pairs       64
//  WI0  [64]  W_ih0[:,0] pairs          64
//  B1   [64]  (b_ih1+b_hh1) pairs       64
//  WO   [7][16] fc1_w[t]*fc_w[h] pairs 112
//  C    [2L][16p][2e][128t]           8192
//  HN0  float[2e][32u][128t]          4096 (u64 units)
//  HN1  float[2e][32u][128t]          4096
// total = 22832 u64 = 182656 B
#define SMEM_U64S 22832
#define SMEM_BYTES (SMEM_U64S * 8)

extern "C" __global__ void __launch_bounds__(128)
lstm_b262144_kernel(
    const float* __restrict__ x,
    const float* __restrict__ Wih0, const float* __restrict__ Whh0,
    const float* __restrict__ bih0, const float* __restrict__ bhh0,
    const float* __restrict__ Wih1, const float* __restrict__ Whh1,
    const float* __restrict__ bih1, const float* __restrict__ bhh1,
    const float* __restrict__ fcw,  const float* __restrict__ fcb,
    const float* __restrict__ fc1w, const float* __restrict__ fc1b,
    float* __restrict__ out, int B)
{
    extern __shared__ u64 sm[];
    u64* WL0  = sm;
    u64* WLX1 = WL0 + 2048;
    u64* WLH1 = WLX1 + 2048;
    u64* B0   = WLH1 + 2048;
    u64* WI0  = B0 + 64;
    u64* B1   = WI0 + 64;
    u64* WO   = B1 + 64;
    u64* C    = WO + 112;
    float* HN0 = (float*)(C + 8192);
    float* HN1 = HN0 + 8192;

    const int tid = threadIdx.x;

    // ---- repack weights: WL[((c*32+k)*8)+s] s={i0,i1,f0,f1,g0,g1,o0,o1} ----
    // s -> gate g=s>>1, sub=s&1; rows r0 = g*32 + 4c + 2*sub, r0+1. col k.
    for (int d = tid; d < 2048; d += 128) {
        int c = d >> 8, k = (d >> 3) & 31, s = d & 7;
        int g = s >> 1, sub = s & 1;
        int r0 = g * 32 + 4 * c + 2 * sub;
        WL0[d]  = pk2(Whh0[r0 * 32 + k], Whh0[(r0 + 1) * 32 + k]);
        WLX1[d] = pk2(Wih1[r0 * 32 + k], Wih1[(r0 + 1) * 32 + k]);
        WLH1[d] = pk2(Whh1[r0 * 32 + k], Whh1[(r0 + 1) * 32 + k]);
    }
    {
        float* B0f  = (float*)B0;
        float* WI0f = (float*)WI0;
        float* B1f  = (float*)B1;
        B0f[tid]  = bih0[tid] + bhh0[tid];
        WI0f[tid] = Wih0[tid];
        B1f[tid]  = bih1[tid] + bhh1[tid];
        float* WOf = (float*)WO;
        for (int d = tid; d < 224; d += 128) WOf[d] = fc1w[d >> 5] * fcw[d & 31];
    }
    // zero per-thread state
#pragma unroll
    for (int u = 0; u < 64; u++) C[u * 128 + tid] = 0ull;
#pragma unroll
    for (int u = 0; u < 64; u++) { HN0[u * 128 + tid] = 0.0f; HN1[u * 128 + tid] = 0.0f; }
    __syncthreads();

    const long long Bll = B;
    long long bA = (long long)blockIdx.x * 256 + tid;
    long long bB = bA + 128;
    if (bA >= Bll) return;
    const long long bBs = (bB < Bll) ? bB : bA;  // safe clamp (dup compute)

    float xa[7], xb[7];
#pragma unroll
    for (int t = 0; t < 7; t++) { xa[t] = x[bA * 7 + t]; xb[t] = x[bBs * 7 + t]; }

    u64 acca = 0ull, accb = 0ull;
    u64 dmy = 0ull;

#pragma unroll 1
    for (int t = 0; t < 7; t++) {
        // ========================= layer 0 =========================
        float h0a[32], h0b[32];
#pragma unroll
        for (int k = 0; k < 32; k++) {
            h0a[k] = HN0[k * 128 + tid];
            h0b[k] = HN0[(32 + k) * 128 + tid];
        }
        u64 x2a = bc2(xa[t]), x2b = bc2(xb[t]);

#pragma unroll 1
        for (int c = 0; c < 8; c++) {
            const int p0 = 2 * c;
            u64 bi0 = B0[p0], bi1 = B0[p0 + 1];
            u64 bf0 = B0[p0 + 16], bf1 = B0[p0 + 17];
            u64 bg0 = B0[p0 + 32], bg1 = B0[p0 + 33];
            u64 bo0 = B0[p0 + 48], bo1 = B0[p0 + 49];
            u64 wi0 = WI0[p0], wi1 = WI0[p0 + 1];
            u64 wf0 = WI0[p0 + 16], wf1 = WI0[p0 + 17];
            u64 wg0 = WI0[p0 + 32], wg1 = WI0[p0 + 33];
            u64 wo0 = WI0[p0 + 48], wo1 = WI0[p0 + 49];

            u64 zai0 = fma2(x2a, wi0, bi0), zbi0 = fma2(x2b, wi0, bi0);
            u64 zai1 = fma2(x2a, wi1, bi1), zbi1 = fma2(x2b, wi1, bi1);
            u64 zaf0 = fma2(x2a, wf0, bf0), zbf0 = fma2(x2b, wf0, bf0);
            u64 zaf1 = fma2(x2a, wf1, bf1), zbf1 = fma2(x2b, wf1, bf1);
            u64 zag0 = fma2(x2a, wg0, bg0), zbg0 = fma2(x2b, wg0, bg0);
            u64 zag1 = fma2(x2a, wg1, bg1), zbg1 = fma2(x2b, wg1, bg1);
            u64 zao0 = fma2(x2a, wo0, bo0), zbo0 = fma2(x2b, wo0, bo0);
            u64 zao1 = fma2(x2a, wo1, bo1), zbo1 = fma2(x2b, wo1, bo1);

            const ulonglong2* wp = (const ulonglong2*)(WL0 + (size_t)c * 256);
#pragma unroll
            for (int k = 0; k < 32; k++) {
                ulonglong2 q0 = wp[4 * k + 0];
                ulonglong2 q1 = wp[4 * k + 1];
                ulonglong2 q2 = wp[4 * k + 2];
                ulonglong2 q3 = wp[4 * k + 3];
                u64 hka = bc2(h0a[k]), hkb = bc2(h0b[k]);
                zai0 = fma2(hka, q0.x, zai0); zbi0 = fma2(hkb, q0.x, zbi0);
                zai1 = fma2(hka, q0.y, zai1); zbi1 = fma2(hkb, q0.y, zbi1);
                zaf0 = fma2(hka, q1.x, zaf0); zbf0 = fma2(hkb, q1.x, zbf0);
                zaf1 = fma2(hka, q1.y, zaf1); zbf1 = fma2(hkb, q1.y, zbf1);
                zag0 = fma2(hka, q2.x, zag0); zbg0 = fma2(hkb, q2.x, zbg0);
                zag1 = fma2(hka, q2.y, zag1); zbg1 = fma2(hkb, q2.y, zbg1);
                zao0 = fma2(hka, q3.x, zao0); zbo0 = fma2(hkb, q3.x, zbo0);
                zao1 = fma2(hka, q3.y, zao1); zbo1 = fma2(hkb, q3.y, zbo1);
            }
            // C layout: (((layer*16 + p)*2 + e)*128 + tid)
            lstm_update<false>(zai0, zaf0, zag0, zao0,
                C + ((p0) * 2 + 0) * 128 + tid,
                &HN0[(2 * p0 + 0) * 128 + tid], &HN0[(2 * p0 + 1) * 128 + tid], 0ull, dmy);
            lstm_update<false>(zai1, zaf1, zag1, zao1,
                C + ((p0 + 1) * 2 + 0) * 128 + tid,
                &HN0[(2 * p0 + 2) * 128 + tid], &HN0[(2 * p0 + 3) * 128 + tid], 0ull, dmy);
            lstm_update<false>(zbi0, zbf0, zbg0, zbo0,
                C + ((p0) * 2 + 1) * 128 + tid,
                &HN0[(32 + 2 * p0 + 0) * 128 + tid], &HN0[(32 + 2 * p0 + 1) * 128 + tid], 0ull, dmy);
            lstm_update<false>(zbi1, zbf1, zbg1, zbo1,
                C + ((p0 + 1) * 2 + 1) * 128 + tid,
                &HN0[(32 + 2 * p0 + 2) * 128 + tid], &HN0[(32 + 2 * p0 + 3) * 128 + tid], 0ull, dmy);
        }

        // ========================= layer 1 =========================
        float g0a[32], g0b[32], h1a[32], h1b[32];
#pragma unroll
        for (int k = 0; k < 32; k++) {
            g0a[k] = HN0[k * 128 + tid];
            g0b[k] = HN0[(32 + k) * 128 + tid];
            h1a[k] = HN1[k * 128 + tid];
            h1b[k] = HN1[(32 + k) * 128 + tid];
        }

#pragma unroll 1
        for (int c = 0; c < 8; c++) {
            const int p0 = 2 * c;
            u64 zai0 = B1[p0],      zai1 = B1[p0 + 1];
            u64 zaf0 = B1[p0 + 16], zaf1 = B1[p0 + 17];
            u64 zag0 = B1[p0 + 32], zag1 = B1[p0 + 33];
            u64 zao0 = B1[p0 + 48], zao1 = B1[p0 + 49];
            u64 zbi0 = zai0, zbi1 = zai1;
            u64 zbf0 = zaf0, zbf1 = zaf1;
            u64 zbg0 = zag0, zbg1 = zag1;
            u64 zbo0 = zao0, zbo1 = zao1;

            const ulonglong2* wpx = (const ulonglong2*)(WLX1 + (size_t)c * 256);
#pragma unroll
            for (int k = 0; k < 32; k++) {
                ulonglong2 q0 = wpx[4 * k + 0];
                ulonglong2 q1 = wpx[4 * k + 1];
                ulonglong2 q2 = wpx[4 * k + 2];
                ulonglong2 q3 = wpx[4 * k + 3];
                u64 hka = bc2(g0a[k]), hkb = bc2(g0b[k]);
                zai0 = fma2(hka, q0.x, zai0); zbi0 = fma2(hkb, q0.x, zbi0);
                zai1 = fma2(hka, q0.y, zai1); zbi1 = fma2(hkb, q0.y, zbi1);
                zaf0 = fma2(hka, q1.x, zaf0); zbf0 = fma2(hkb, q1.x, zbf0);
                zaf1 = fma2(hka, q1.y, zaf1); zbf1 = fma2(hkb, q1.y, zbf1);
                zag0 = fma2(hka, q2.x, zag0); zbg0 = fma2(hkb, q2.x, zbg0);
                zag1 = fma2(hka, q2.y, zag1); zbg1 = fma2(hkb, q2.y, zbg1);
                zao0 = fma2(hka, q3.x, zao0); zbo0 = fma2(hkb, q3.x, zbo0);
                zao1 = fma2(hka, q3.y, zao1); zbo1 = fma2(hkb, q3.y, zbo1);
            }
            const ulonglong2* wph = (const ulonglong2*)(WLH1 + (size_t)c * 256);
#pragma unroll
            for (int k = 0; k < 32; k++) {
                ulonglong2 q0 = wph[4 * k + 0];
                ulonglong2 q1 = wph[4 * k + 1];
                ulonglong2 q2 = wph[4 * k + 2];
                ulonglong2 q3 = wph[4 * k + 3];
                u64 hka = bc2(h1a[k]), hkb = bc2(h1b[k]);
                zai0 = fma2(hka, q0.x, zai0); zbi0 = fma2(hkb, q0.x, zbi0);
                zai1 = fma2(hka, q0.y, zai1); zbi1 = fma2(hkb, q0.y, zbi1);
                zaf0 = fma2(hka, q1.x, zaf0); zbf0 = fma2(hkb, q1.x, zbf0);
                zaf1 = fma2(hka, q1.y, zaf1); zbf1 = fma2(hkb, q1.y, zbf1);
                zag0 = fma2(hka, q2.x, zag0); zbg0 = fma2(hkb, q2.x, zbg0);
                zag1 = fma2(hka, q2.y, zag1); zbg1 = fma2(hkb, q2.y, zbg1);
                zao0 = fma2(hka, q3.x, zao0); zbo0 = fma2(hkb, q3.x, zbo0);
                zao1 = fma2(hka, q3.y, zao1); zbo1 = fma2(hkb, q3.y, zbo1);
            }
            u64 wo_p0 = WO[t * 16 + p0], wo_p1 = WO[t * 16 + p0 + 1];
            lstm_update<true>(zai0, zaf0, zag0, zao0,
                C + ((16 + p0) * 2 + 0) * 128 + tid,
                &HN1[(2 * p0 + 0) * 128 + tid], &HN1[(2 * p0 + 1) * 128 + tid], wo_p0, acca);
            lstm_update<true>(zai1, zaf1, zag1, zao1,
                C + ((16 + p0 + 1) * 2 + 0) * 128 + tid,
                &HN1[(2 * p0 + 2) * 128 + tid], &HN1[(2 * p0 + 3) * 128 + tid], wo_p1, acca);
            lstm_update<true>(zbi0, zbf0, zbg0, zbo0,
                C + ((16 + p0) * 2 + 1) * 128 + tid,
                &HN1[(32 + 2 * p0 + 0) * 128 + tid], &HN1[(32 + 2 * p0 + 1) * 128 + tid], wo_p0, accb);
            lstm_update<true>(zbi1, zbf1, zbg1, zbo1,
                C + ((16 + p0 + 1) * 2 + 1) * 128 + tid,
                &HN1[(32 + 2 * p0 + 2) * 128 + tid], &HN1[(32 + 2 * p0 + 3) * 128 + tid], wo_p1, accb);
        }
    }

    // y = Σ(acc) + fc_b*Σ_t fc1_w[t] + fc1_b
    float s = 0.0f;
#pragma unroll
    for (int t = 0; t < 7; t++) s += fc1w[t];
    float bias = fcb[0] * s + fc1b[0];

    float alo, ahi; upk2(acca, alo, ahi);
    out[bA] = alo + ahi + bias;
    if (bB < Bll) {
        float blo, bhi; upk2(accb, blo, bhi);
        out[bB] = blo + bhi + bias;
    }
}

extern "C" void kernel_launch(void* const* d_in, const int* in_sizes, int n_in,
                              void* d_out, int out_size) {
    const float* x    = (const float*)d_in[0];
    const float* Wih0 = (const float*)d_in[1];
    const float* Whh0 = (const float*)d_in[2];
    const float* bih0 = (const float*)d_in[3];
    const float* bhh0 = (const float*)d_in[4];
    const float* Wih1 = (const float*)d_in[5];
    const float* Whh1 = (const float*)d_in[6];
    const float* bih1 = (const float*)d_in[7];
    const float* bhh1 = (const float*)d_in[8];
    const float* fcw  = (const float*)d_in[9];
    const float* fcb  = (const float*)d_in[10];
    const float* fc1w = (const float*)d_in[11];
    const float* fc1b = (const float*)d_in[12];
    float* out = (float*)d_out;

    const int B = in_sizes[0] / 7;  // [B, T=7, F=1]

    cudaFuncSetAttribute(lstm_b262144_kernel,
                         cudaFuncAttributeMaxDynamicSharedMemorySize, SMEM_BYTES);

    int grid = (B + 255) / 256;  // 256 batch elems per CTA (2 per thread)
    lstm_b262144_kernel<<<grid, 128, SMEM_BYTES>>>(
        x, Wih0, Whh0, bih0, bhh0, Wih1, Whh1, bih1, bhh1,
        fcw, fcb, fc1w, fc1b, out, B);
}

// round 4
// speedup vs baseline: 1.6204x; 1.5258x over previous
#include <cuda_runtime.h>
#include <cuda_bf16.h>
#include <cstdint>

// ============================================================================
// 2-layer LSTM (H=32, T=7, F=1) + Linear(H,1) + Linear(T,1), B=262144.
// R3: ONE batch element per thread, 256 threads/CTA -> 8 warps/SM (2/SMSP)
// to hide LDS/MUFU latency (R2 was latency-bound at 4 warps/SM).
// Weights repacked in SMEM as [chunk][k][8 gate-pair u64] -> 4x LDS.128
// broadcast feeds 8 FFMA2 per k-iter. h-state in registers (unrolled k),
// c-state + h staging in per-thread SMEM slots (rolled chunk loop, small I$).
// ============================================================================

typedef unsigned long long u64;

#define NT 256  // threads per CTA

__device__ __forceinline__ u64 pk2(float lo, float hi) {
    u64 r; asm("mov.b64 %0,{%1,%2};" : "=l"(r) : "f"(lo), "f"(hi)); return r;
}
__device__ __forceinline__ u64 bc2(float v) { return pk2(v, v); }
__device__ __forceinline__ void upk2(u64 v, float& lo, float& hi) {
    asm("mov.b64 {%0,%1},%2;" : "=f"(lo), "=f"(hi) : "l"(v));
}
__device__ __forceinline__ u64 fma2(u64 a, u64 b, u64 c) {
    u64 d; asm("fma.rn.f32x2 %0,%1,%2,%3;" : "=l"(d) : "l"(a), "l"(b), "l"(c)); return d;
}
__device__ __forceinline__ u64 mul2(u64 a, u64 b) {
    u64 d; asm("mul.rn.f32x2 %0,%1,%2;" : "=l"(d) : "l"(a), "l"(b)); return d;
}
__device__ __forceinline__ float ex2f(float x) {
    float y; asm("ex2.approx.f32 %0,%1;" : "=f"(y) : "f"(x)); return y;
}
__device__ __forceinline__ float rcpf(float x) {
    float y; asm("rcp.approx.f32 %0,%1;" : "=f"(y) : "f"(x)); return y;
}
__device__ __forceinline__ float fsig(float x) {
    float e = ex2f(-1.4426950408889634f * x);
    return rcpf(1.0f + e);
}
__device__ __forceinline__ float ftanhx(float x) {
    float t = fminf(-2.8853900817779268f * x, 120.0f);
    float e = ex2f(t);
    float r = rcpf(1.0f + e);
    return fmaf(-e, r, r);
}
__device__ __forceinline__ u64 sig2(u64 z) {
    float a, b; upk2(z, a, b); return pk2(fsig(a), fsig(b));
}
__device__ __forceinline__ u64 tanh2(u64 z) {
    float a, b; upk2(z, a, b); return pk2(ftanhx(a), ftanhx(b));
}

// One unit-pair gate update. z* packed (unit 2p, 2p+1) preactivations.
template <bool DOACC>
__device__ __forceinline__ void lstm_update(
    u64 zi, u64 zf, u64 zg, u64 zo,
    u64* cslot, float* hn_lo, float* hn_hi,
    u64 wo, u64& acc)
{
    u64 i2 = sig2(zi);
    u64 f2 = sig2(zf);
    u64 g2 = tanh2(zg);
    u64 o2 = sig2(zo);
    u64 cc = *cslot;
    cc = fma2(f2, cc, mul2(i2, g2));
    *cslot = cc;
    u64 h2 = mul2(o2, tanh2(cc));
    if (DOACC) acc = fma2(h2, wo, acc);
    float lo, hi; upk2(h2, lo, hi);
    *hn_lo = lo; *hn_hi = hi;
}

// SMEM layout (u64 units):
//  WL0  [8c][32k][8s] repacked Whh0      2048
//  WLX1 [8c][32k][8s] repacked Wih1      2048
//  WLH1 [8c][32k][8s] repacked Whh1      2048
//  B0   [64]  (b_ih0+b_hh0) pairs          64
//  WI0  [64]  W_ih0[:,0] pairs             64
//  B1   [64]  (b_ih1+b_hh1) pairs          64
//  WO   [7][16] fc1_w[t]*fc_w[h] pairs    112
//  C    [2L*16p][256t] cell state        8192
//  HN0  float[32u][256t]                 4096
//  HN1  float[32u][256t]                 4096
// total = 22832 u64 = 182656 B
#define SMEM_U64S 22832
#define SMEM_BYTES (SMEM_U64S * 8)

extern "C" __global__ void __launch_bounds__(NT, 1)
lstm_b262144_kernel(
    const float* __restrict__ x,
    const float* __restrict__ Wih0, const float* __restrict__ Whh0,
    const float* __restrict__ bih0, const float* __restrict__ bhh0,
    const float* __restrict__ Wih1, const float* __restrict__ Whh1,
    const float* __restrict__ bih1, const float* __restrict__ bhh1,
    const float* __restrict__ fcw,  const float* __restrict__ fcb,
    const float* __restrict__ fc1w, const float* __restrict__ fc1b,
    float* __restrict__ out, int B)
{
    extern __shared__ u64 sm[];
    u64* WL0  = sm;
    u64* WLX1 = WL0 + 2048;
    u64* WLH1 = WLX1 + 2048;
    u64* B0   = WLH1 + 2048;
    u64* WI0  = B0 + 64;
    u64* B1   = WI0 + 64;
    u64* WO   = B1 + 64;
    u64* C    = WO + 112;
    float* HN0 = (float*)(C + 8192);
    float* HN1 = HN0 + 8192;

    const int tid = threadIdx.x;

    // ---- repack weights: WL[((c*32+k)*8)+s] s={i0,i1,f0,f1,g0,g1,o0,o1} ----
    // s -> gate g=s>>1, sub=s&1; rows r0 = g*32 + 4c + 2*sub, r0+1. col k.
    for (int d = tid; d < 2048; d += NT) {
        int c = d >> 8, k = (d >> 3) & 31, s = d & 7;
        int g = s >> 1, sub = s & 1;
        int r0 = g * 32 + 4 * c + 2 * sub;
        WL0[d]  = pk2(Whh0[r0 * 32 + k], Whh0[(r0 + 1) * 32 + k]);
        WLX1[d] = pk2(Wih1[r0 * 32 + k], Wih1[(r0 + 1) * 32 + k]);
        WLH1[d] = pk2(Whh1[r0 * 32 + k], Whh1[(r0 + 1) * 32 + k]);
    }
    if (tid < 128) {
        float* B0f  = (float*)B0;
        float* WI0f = (float*)WI0;
        float* B1f  = (float*)B1;
        B0f[tid]  = bih0[tid] + bhh0[tid];
        WI0f[tid] = Wih0[tid];
        B1f[tid]  = bih1[tid] + bhh1[tid];
    }
    {
        float* WOf = (float*)WO;
        for (int d = tid; d < 224; d += NT) WOf[d] = fc1w[d >> 5] * fcw[d & 31];
    }
    // zero per-thread state
#pragma unroll
    for (int u = 0; u < 32; u++) C[u * NT + tid] = 0ull;
#pragma unroll
    for (int u = 0; u < 32; u++) { HN0[u * NT + tid] = 0.0f; HN1[u * NT + tid] = 0.0f; }
    __syncthreads();

    const long long b = (long long)blockIdx.x * NT + tid;
    if (b >= B) return;

    float xv[7];
#pragma unroll
    for (int t = 0; t < 7; t++) xv[t] = x[b * 7 + t];

    u64 acc = 0ull;
    u64 dmy = 0ull;

#pragma unroll 1
    for (int t = 0; t < 7; t++) {
        // ========================= layer 0 =========================
        float h0[32];
#pragma unroll
        for (int k = 0; k < 32; k++) h0[k] = HN0[k * NT + tid];
        u64 x2 = bc2(xv[t]);

#pragma unroll 1
        for (int c = 0; c < 8; c++) {
            const int p0 = 2 * c;
            u64 zi0 = fma2(x2, WI0[p0 + 0],  B0[p0 + 0]);
            u64 zi1 = fma2(x2, WI0[p0 + 1],  B0[p0 + 1]);
            u64 zf0 = fma2(x2, WI0[p0 + 16], B0[p0 + 16]);
            u64 zf1 = fma2(x2, WI0[p0 + 17], B0[p0 + 17]);
            u64 zg0 = fma2(x2, WI0[p0 + 32], B0[p0 + 32]);
            u64 zg1 = fma2(x2, WI0[p0 + 33], B0[p0 + 33]);
            u64 zo0 = fma2(x2, WI0[p0 + 48], B0[p0 + 48]);
            u64 zo1 = fma2(x2, WI0[p0 + 49], B0[p0 + 49]);

            const ulonglong2* wp = (const ulonglong2*)(WL0 + (size_t)c * 256);
#pragma unroll
            for (int k = 0; k < 32; k++) {
                ulonglong2 q0 = wp[4 * k + 0];
                ulonglong2 q1 = wp[4 * k + 1];
                ulonglong2 q2 = wp[4 * k + 2];
                ulonglong2 q3 = wp[4 * k + 3];
                u64 hk = bc2(h0[k]);
                zi0 = fma2(hk, q0.x, zi0);
                zi1 = fma2(hk, q0.y, zi1);
                zf0 = fma2(hk, q1.x, zf0);
                zf1 = fma2(hk, q1.y, zf1);
                zg0 = fma2(hk, q2.x, zg0);
                zg1 = fma2(hk, q2.y, zg1);
                zo0 = fma2(hk, q3.x, zo0);
                zo1 = fma2(hk, q3.y, zo1);
            }
            lstm_update<false>(zi0, zf0, zg0, zo0,
                C + (p0) * NT + tid,
                &HN0[(2 * p0 + 0) * NT + tid], &HN0[(2 * p0 + 1) * NT + tid], 0ull, dmy);
            lstm_update<false>(zi1, zf1, zg1, zo1,
                C + (p0 + 1) * NT + tid,
                &HN0[(2 * p0 + 2) * NT + tid], &HN0[(2 * p0 + 3) * NT + tid], 0ull, dmy);
        }

        // ========================= layer 1 =========================
        float g0[32], h1[32];
#pragma unroll
        for (int k = 0; k < 32; k++) {
            g0[k] = HN0[k * NT + tid];
            h1[k] = HN1[k * NT + tid];
        }

#pragma unroll 1
        for (int c = 0; c < 8; c++) {
            const int p0 = 2 * c;
            u64 zi0 = B1[p0],      zi1 = B1[p0 + 1];
            u64 zf0 = B1[p0 + 16], zf1 = B1[p0 + 17];
            u64 zg0 = B1[p0 + 32], zg1 = B1[p0 + 33];
            u64 zo0 = B1[p0 + 48], zo1 = B1[p0 + 49];

            const ulonglong2* wpx = (const ulonglong2*)(WLX1 + (size_t)c * 256);
#pragma unroll
            for (int k = 0; k < 32; k++) {
                ulonglong2 q0 = wpx[4 * k + 0];
                ulonglong2 q1 = wpx[4 * k + 1];
                ulonglong2 q2 = wpx[4 * k + 2];
                ulonglong2 q3 = wpx[4 * k + 3];
                u64 hk = bc2(g0[k]);
                zi0 = fma2(hk, q0.x, zi0);
                zi1 = fma2(hk, q0.y, zi1);
                zf0 = fma2(hk, q1.x, zf0);
                zf1 = fma2(hk, q1.y, zf1);
                zg0 = fma2(hk, q2.x, zg0);
                zg1 = fma2(hk, q2.y, zg1);
                zo0 = fma2(hk, q3.x, zo0);
                zo1 = fma2(hk, q3.y, zo1);
            }
            const ulonglong2* wph = (const ulonglong2*)(WLH1 + (size_t)c * 256);
#pragma unroll
            for (int k = 0; k < 32; k++) {
                ulonglong2 q0 = wph[4 * k + 0];
                ulonglong2 q1 = wph[4 * k + 1];
                ulonglong2 q2 = wph[4 * k + 2];
                ulonglong2 q3 = wph[4 * k + 3];
                u64 hk = bc2(h1[k]);
                zi0 = fma2(hk, q0.x, zi0);
                zi1 = fma2(hk, q0.y, zi1);
                zf0 = fma2(hk, q1.x, zf0);
                zf1 = fma2(hk, q1.y, zf1);
                zg0 = fma2(hk, q2.x, zg0);
                zg1 = fma2(hk, q2.y, zg1);
                zo0 = fma2(hk, q3.x, zo0);
                zo1 = fma2(hk, q3.y, zo1);
            }
            u64 wo_p0 = WO[t * 16 + p0], wo_p1 = WO[t * 16 + p0 + 1];
            lstm_update<true>(zi0, zf0, zg0, zo0,
                C + (16 + p0) * NT + tid,
                &HN1[(2 * p0 + 0) * NT + tid], &HN1[(2 * p0 + 1) * NT + tid], wo_p0, acc);
            lstm_update<true>(zi1, zf1, zg1, zo1,
                C + (16 + p0 + 1) * NT + tid,
                &HN1[(2 * p0 + 2) * NT + tid], &HN1[(2 * p0 + 3) * NT + tid], wo_p1, acc);
        }
    }

    // y = Σ(acc) + fc_b*Σ_t fc1_w[t] + fc1_b
    float s = 0.0f;
#pragma unroll
    for (int t = 0; t < 7; t++) s += fc1w[t];
    float alo, ahi; upk2(acc, alo, ahi);
    out[b] = alo + ahi + fcb[0] * s + fc1b[0];
}

extern "C" void kernel_launch(void* const* d_in, const int* in_sizes, int n_in,
                              void* d_out, int out_size) {
    const float* x    = (const float*)d_in[0];
    const float* Wih0 = (const float*)d_in[1];
    const float* Whh0 = (const float*)d_in[2];
    const float* bih0 = (const float*)d_in[3];
    const float* bhh0 = (const float*)d_in[4];
    const float* Wih1 = (const float*)d_in[5];
    const float* Whh1 = (const float*)d_in[6];
    const float* bih1 = (const float*)d_in[7];
    const float* bhh1 = (const float*)d_in[8];
    const float* fcw  = (const float*)d_in[9];
    const float* fcb  = (const float*)d_in[10];
    const float* fc1w = (const float*)d_in[11];
    const float* fc1b = (const float*)d_in[12];
    float* out = (float*)d_out;

    const int B = in_sizes[0] / 7;  // [B, T=7, F=1]

    cudaFuncSetAttribute(lstm_b262144_kernel,
                         cudaFuncAttributeMaxDynamicSharedMemorySize, SMEM_BYTES);

    int grid = (B + NT - 1) / NT;
    lstm_b262144_kernel<<<grid, NT, SMEM_BYTES>>>(
        x, Wih0, Whh0, bih0, bhh0, Wih1, Whh1, bih1, bhh1,
        fcw, fcb, fc1w, fc1b, out, B);
}